// round 16
// baseline (speedup 1.0000x reference)
#include <cuda_runtime.h>
#include <cstdint>

// Problem constants
#define BB   64
#define TT   512
#define NTOT 32768      // BB*TT
#define FF   1024
#define DD   128

// Scratch (device globals; no allocation allowed)
__device__ float g_M[BB * DD];          // sum over t of lrelu(e1)
__device__ unsigned g_cnt[BB];          // CTA-completion counters per batch
__device__ unsigned g_wb[DD * (FF/2)];  // fc1_w bf16x2, layout [m][k2]
__device__ unsigned g_w1hi[DD * 64];    // emb_w1 hi bf16x2, layout [j][k2]
__device__ unsigned g_w1lo[DD * 64];    // emb_w1 lo residual bf16x2

// ---------------------------------------------------------------- helpers
__device__ __forceinline__ float mtanh(float x) {
    float y;
    asm("tanh.approx.f32 %0, %1;" : "=f"(y) : "f"(x));
    return y;
}
__device__ __forceinline__ unsigned sptr(const void* p) {
    return (unsigned)__cvta_generic_to_shared(p);
}
__device__ __forceinline__ void cp16(unsigned dst, const void* src) {
    asm volatile("cp.async.cg.shared.global [%0], [%1], 16;" :: "r"(dst), "l"(src));
}
#define CP_COMMIT() asm volatile("cp.async.commit_group;")
#define CP_WAIT0()  asm volatile("cp.async.wait_group 0;")

__device__ __forceinline__ unsigned pack_bf2(float kodd, float keven) {
    unsigned d;
    asm("cvt.rn.bf16x2.f32 %0, %1, %2;" : "=r"(d) : "f"(kodd), "f"(keven));
    return d;
}
__device__ __forceinline__ float bf_lo_val(unsigned p) { return __uint_as_float(p << 16); }
__device__ __forceinline__ float bf_hi_val(unsigned p) { return __uint_as_float(p & 0xffff0000u); }
__device__ __forceinline__ unsigned hadd2(unsigned a, unsigned b) {
    unsigned d;
    asm("add.rn.bf16x2 %0, %1, %2;" : "=r"(d) : "r"(a), "r"(b));
    return d;
}
__device__ __forceinline__ void ldsm_x4(unsigned r[4], unsigned addr) {
    asm volatile("ldmatrix.sync.aligned.m8n8.x4.shared.b16 {%0,%1,%2,%3}, [%4];"
                 : "=r"(r[0]), "=r"(r[1]), "=r"(r[2]), "=r"(r[3]) : "r"(addr));
}
__device__ __forceinline__ void mma_bf16(float c[4], const unsigned a[4], const unsigned b[2]) {
    asm volatile(
        "mma.sync.aligned.m16n8k16.row.col.f32.bf16.bf16.f32 "
        "{%0,%1,%2,%3}, {%4,%5,%6,%7}, {%8,%9}, {%0,%1,%2,%3};"
        : "+f"(c[0]), "+f"(c[1]), "+f"(c[2]), "+f"(c[3])
        : "r"(a[0]), "r"(a[1]), "r"(a[2]), "r"(a[3]), "r"(b[0]), "r"(b[1]));
}

// ============================================================================
// Kernel 0: prep — fc1_w -> g_wb [m][k2] (float4 path, 4 pairs/thread);
// emb_w1 -> hi/lo split; zero g_M and g_cnt.
// ============================================================================
__global__ __launch_bounds__(256) void prep_kernel(const float* __restrict__ w,
                                                   const float* __restrict__ w1)
{
    const int t = blockIdx.x * 256 + threadIdx.x;   // 0..16383
    {
        const float4 a = *reinterpret_cast<const float4*>(w + (size_t)t * 8);
        const float4 b = *reinterpret_cast<const float4*>(w + (size_t)t * 8 + 4);
        const int m  = t >> 7;              // 0..127
        const int k2 = (t & 127) * 4;       // 0..508
        unsigned* dst = g_wb + m * 512 + k2;
        dst[0] = pack_bf2(a.y, a.x);
        dst[1] = pack_bf2(a.w, a.z);
        dst[2] = pack_bf2(b.y, b.x);
        dst[3] = pack_bf2(b.w, b.z);
    }
    if (t < DD * 64) {
        const int j  = t >> 6;
        const int k2 = t & 63;
        const float a0 = w1[j * DD + 2 * k2];
        const float a1 = w1[j * DD + 2 * k2 + 1];
        const unsigned hi = pack_bf2(a1, a0);
        const float l0 = a0 - bf_lo_val(hi);
        const float l1 = a1 - bf_hi_val(hi);
        g_w1hi[t] = hi;
        g_w1lo[t] = pack_bf2(l1, l0);
    }
    if (t < BB * DD) g_M[t] = 0.f;
    if (t < BB) g_cnt[t] = 0u;
}

// ============================================================================
// MEGAKERNEL: fc1 (bf16 HMMA) -> bi-LSTM -> emb1 (bf16 split HMMA) -> final
// per-batch GEMV (done by the last-arriving CTA of each batch), fully fused.
// ============================================================================
#define P1A_U 2560                 // 128 rows x 20 (phase-1 A stage)
#define P1B_U 2176                 // 16 rows x 136 (phase-1 B stage)
#define RING_U (2*P1A_U + 2*P1B_U) // 9472 uints
#define SG_ST 65                   // G smem row stride (u32 pairs, padded)
#define P3A_U 1536                 // 128 rows x 12 (phase-3 A stage; reuses G region)
#define SY_ST 136
#define SY_U  (64 * SY_ST)         // 8704 uints per Y buffer
#define MEGA_U (RING_U + 2 * SY_U) // 26880 uints
#define MEGA_B (MEGA_U * 4)        // 107520 bytes

__global__ __launch_bounds__(256, 2) void mega_kernel(
    const float* __restrict__ x,    const float* __restrict__ fc1_b,
    const float* __restrict__ wih_f, const float* __restrict__ whh_f,
    const float* __restrict__ bih_f, const float* __restrict__ bhh_f,
    const float* __restrict__ wih_b, const float* __restrict__ whh_b,
    const float* __restrict__ bih_b, const float* __restrict__ bhh_b,
    const float* __restrict__ lout_w, const float* __restrict__ lout_b,
    const float* __restrict__ b1v,
    const float* __restrict__ w2, const float* __restrict__ b2,
    float* __restrict__ out)
{
    extern __shared__ __align__(16) unsigned smu[];
    unsigned* A_[2]; unsigned* B_[2];
    A_[0] = smu;             A_[1] = smu + P1A_U;
    B_[0] = smu + 2 * P1A_U; B_[1] = smu + 2 * P1A_U + P1B_U;
    unsigned* sG  = smu;                 // phase-1 epilogue .. phase-2 (8320 u)
    unsigned* sYf = smu + RING_U;
    unsigned* sYb = smu + RING_U + SY_U;

    __shared__ float sm_m[128];
    __shared__ unsigned s_last;

    const int tid  = threadIdx.x;
    const int lane = tid & 31;
    const int wid  = tid >> 5;
    const int g    = lane >> 2;
    const int tig  = lane & 3;
    const int wm   = (wid & 1) * 64;
    const int wn   = (wid >> 1) * 32;

    const int bt = blockIdx.y;
    const int t0 = blockIdx.x * 128;
    const float* xb = x + (size_t)bt * FF * TT;

    const int rowA  = tid >> 1;
    const int halfA = (tid & 1) * 8;
    const int kr = tid >> 4;
    const int q8 = (tid & 15) * 8;

    const unsigned lrow = wm + (lane & 7) + ((lane >> 3) & 1) * 8;
    const unsigned lak  = ((lane >> 4) & 1) * 4;

    float c[4][4][4];
#pragma unroll
    for (int i = 0; i < 4; i++)
#pragma unroll
        for (int j = 0; j < 4; j++)
#pragma unroll
            for (int k = 0; k < 4; k++) c[i][j][k] = 0.f;

    // ======================= Phase 1: fc1 GEMM =======================
    {
        const int NS = FF / 32;   // 32 stages

        // prologue: A(0)
        {
            const unsigned* srcA = g_wb + rowA * 512 + halfA;
            unsigned dst = sptr(A_[0] + rowA * 20 + halfA);
            cp16(dst, srcA); cp16(dst + 16, srcA + 4);
            CP_COMMIT();
        }
        float4 u0, u1, v0, v1;
        {
            const float* xp = xb + (size_t)(2 * kr) * TT + t0 + q8;
            u0 = *reinterpret_cast<const float4*>(xp);
            u1 = *reinterpret_cast<const float4*>(xp + 4);
            v0 = *reinterpret_cast<const float4*>(xp + TT);
            v1 = *reinterpret_cast<const float4*>(xp + TT + 4);
        }

        for (int s = 0; s < NS; s++) {
            // pack + store B(s)
            {
                unsigned* bp = B_[s & 1] + kr * 136 + q8;
                const float ue[8] = {u0.x, u0.y, u0.z, u0.w, u1.x, u1.y, u1.z, u1.w};
                const float vo[8] = {v0.x, v0.y, v0.z, v0.w, v1.x, v1.y, v1.z, v1.w};
                unsigned h[8];
#pragma unroll
                for (int i = 0; i < 8; i++) h[i] = pack_bf2(vo[i], ue[i]);
                *reinterpret_cast<uint4*>(bp)     = make_uint4(h[0], h[1], h[2], h[3]);
                *reinterpret_cast<uint4*>(bp + 4) = make_uint4(h[4], h[5], h[6], h[7]);
            }
            CP_WAIT0();          // A(s) landed
            __syncthreads();     // B(s) visible; buffer (s+1)&1 free

            if (s + 1 < NS) {
                const unsigned* srcA = g_wb + rowA * 512 + (s + 1) * 16 + halfA;
                unsigned dst = sptr(A_[(s + 1) & 1] + rowA * 20 + halfA);
                cp16(dst, srcA); cp16(dst + 16, srcA + 4);
            }
            CP_COMMIT();

            // prefetch B(s+1)
            {
                const int sn = (s + 1 < NS) ? s + 1 : s;
                const float* xp = xb + (size_t)(sn * 32 + 2 * kr) * TT + t0 + q8;
                u0 = *reinterpret_cast<const float4*>(xp);
                u1 = *reinterpret_cast<const float4*>(xp + 4);
                v0 = *reinterpret_cast<const float4*>(xp + TT);
                v1 = *reinterpret_cast<const float4*>(xp + TT + 4);
            }

            const unsigned Abase = sptr(A_[s & 1]);
            const unsigned* B = B_[s & 1];
#pragma unroll
            for (int g16 = 0; g16 < 2; g16++) {
                unsigned a[4][4], b[4][2];
#pragma unroll
                for (int mt = 0; mt < 4; mt++) {
                    const unsigned ad = Abase + ((lrow + mt * 16) * 20 + g16 * 8 + lak) * 4;
                    ldsm_x4(a[mt], ad);
                }
#pragma unroll
                for (int nt = 0; nt < 4; nt++) {
                    const int n = wn + nt * 8 + g;
                    b[nt][0] = B[(g16 * 8 + tig) * 136 + n];
                    b[nt][1] = B[(g16 * 8 + tig + 4) * 136 + n];
                }
#pragma unroll
                for (int mt = 0; mt < 4; mt++)
#pragma unroll
                    for (int nt = 0; nt < 4; nt++)
                        mma_bf16(c[mt][nt], a[mt], b[nt]);
            }
        }

        CP_WAIT0();
        __syncthreads();   // all MMAs done: ring region reusable as sG

        // epilogue: bias + pack to bf16 n-pairs in smem sG[d][n2]
#pragma unroll
        for (int mt = 0; mt < 4; mt++) {
            const int dr = wm + mt * 16 + g;
            const float bv0 = fc1_b[dr];
            const float bv1 = fc1_b[dr + 8];
#pragma unroll
            for (int nt = 0; nt < 4; nt++) {
                const int n2 = (wn + nt * 8) / 2 + tig;   // n-pair column
                sG[dr * SG_ST + n2] =
                    pack_bf2(c[mt][nt][1] + bv0, c[mt][nt][0] + bv0);
                sG[(dr + 8) * SG_ST + n2] =
                    pack_bf2(c[mt][nt][3] + bv1, c[mt][nt][2] + bv1);
            }
        }
    }
    __syncthreads();   // sG complete

    // ======================= Phase 2: bi-LSTM (smem-resident) ================
    {
        const int dir = tid >> 7;          // 0 fwd, 1 bwd
        const int nl  = tid & 127;

        const float* wih = dir ? wih_b : wih_f;
        const float* whh = dir ? whh_b : whh_f;
        const float* bih = dir ? bih_b : bih_f;
        const float* bhh = dir ? bhh_b : bhh_f;

        const float wi0 = 0.5f * wih[0], wh0 = 0.5f * whh[0], b0 = 0.5f * (bih[0] + bhh[0]);
        const float wi1 = 0.5f * wih[1], wh1 = 0.5f * whh[1], b1 = 0.5f * (bih[1] + bhh[1]);
        const float wi2 =        wih[2], wh2 =        whh[2], b2g =        (bih[2] + bhh[2]);
        const float wi3 = 0.5f * wih[3], wh3 = 0.5f * whh[3], b3 = 0.5f * (bih[3] + bhh[3]);

        const float lw = dir ? lout_w[1] : lout_w[0];
        const float lb = dir ? 0.f : lout_b[0];

        const int gst = dir ? -SG_ST : SG_ST;
        const unsigned* gp = sG + (dir ? 127 * SG_ST : 0) + (nl >> 1);
        const bool hi_half = (nl & 1);

        unsigned* yw = (dir ? (sYb + 63 * SY_ST) : sYf) + nl;
        const int yst = dir ? -SY_ST : SY_ST;

        float h = 0.f, cc = 0.f, yprev = 0.f;

#pragma unroll 8
        for (int it = 0; it < DD; it++) {
            const unsigned gw = *gp;
            gp += gst;
            const float xv = hi_half ? bf_hi_val(gw) : bf_lo_val(gw);

            const float ai = fmaf(wi0, xv, fmaf(wh0, h, b0));
            const float af = fmaf(wi1, xv, fmaf(wh1, h, b1));
            const float ag = fmaf(wi2, xv, fmaf(wh2, h, b2g));
            const float ao = fmaf(wi3, xv, fmaf(wh3, h, b3));

            const float si = fmaf(0.5f, mtanh(ai), 0.5f);
            const float sf = fmaf(0.5f, mtanh(af), 0.5f);
            const float tg = mtanh(ag);
            const float so = fmaf(0.5f, mtanh(ao), 0.5f);

            cc = fmaf(sf, cc, si * tg);
            h = so * mtanh(cc);

            const float y = fmaf(lw, h, lb);
            if (it & 1) {
                *yw = dir ? pack_bf2(yprev, y) : pack_bf2(y, yprev);
                yw += yst;
            } else {
                yprev = y;
            }
        }
    }
    __syncthreads();   // sYf / sYb ready; sG dead

    // ======================= Phase 3: emb1 =======================
    {
        unsigned* AH_[2]; unsigned* AL_[2];
        AH_[0] = smu;             AH_[1] = smu + P3A_U;
        AL_[0] = smu + 2 * P3A_U; AL_[1] = smu + 3 * P3A_U;

        const int rowW  = tid >> 1;
        const int halfW = (tid & 1) * 4;

#pragma unroll
        for (int i = 0; i < 4; i++)
#pragma unroll
            for (int j = 0; j < 4; j++)
#pragma unroll
                for (int k = 0; k < 4; k++) c[i][j][k] = 0.f;

        // prologue: stage 0
        cp16(sptr(AH_[0] + rowW * 12 + halfW), g_w1hi + rowW * 64 + halfW);
        cp16(sptr(AL_[0] + rowW * 12 + halfW), g_w1lo + rowW * 64 + halfW);
        CP_COMMIT();

        for (int s = 0; s < 8; s++) {        // 8 stages of 8 k2-rows (k16 each)
            CP_WAIT0();          // A(s) landed
            __syncthreads();     // all warps past MMA(s-1): buffer (s+1)&1 free

            if (s + 1 < 8) {
                cp16(sptr(AH_[(s + 1) & 1] + rowW * 12 + halfW),
                     g_w1hi + rowW * 64 + (s + 1) * 8 + halfW);
                cp16(sptr(AL_[(s + 1) & 1] + rowW * 12 + halfW),
                     g_w1lo + rowW * 64 + (s + 1) * 8 + halfW);
            }
            CP_COMMIT();

            const unsigned AHb = sptr(AH_[s & 1]);
            const unsigned ALb = sptr(AL_[s & 1]);

            unsigned ah[4][4], al[4][4], b[4][2];
#pragma unroll
            for (int mt = 0; mt < 4; mt++) {
                const unsigned off = ((lrow + mt * 16) * 12 + lak) * 4;
                ldsm_x4(ah[mt], AHb + off);
                ldsm_x4(al[mt], ALb + off);
            }
#pragma unroll
            for (int nt = 0; nt < 4; nt++) {
                const int n = wn + nt * 8 + g;
                b[nt][0] = hadd2(sYf[(s * 8 + tig) * SY_ST + n],
                                 sYb[(s * 8 + tig) * SY_ST + n]);
                b[nt][1] = hadd2(sYf[(s * 8 + tig + 4) * SY_ST + n],
                                 sYb[(s * 8 + tig + 4) * SY_ST + n]);
            }
#pragma unroll
            for (int mt = 0; mt < 4; mt++)
#pragma unroll
                for (int nt = 0; nt < 4; nt++) {
                    mma_bf16(c[mt][nt], ah[mt], b[nt]);
                    mma_bf16(c[mt][nt], al[mt], b[nt]);
                }
        }

        // epilogue: bias + leaky-relu + sum over n, quad-reduce, atomicAdd
#pragma unroll
        for (int mt = 0; mt < 4; mt++) {
            const int jr = wm + mt * 16 + g;
            const float bv0 = b1v[jr];
            const float bv1 = b1v[jr + 8];
            float s0 = 0.f, s1 = 0.f;
#pragma unroll
            for (int nt = 0; nt < 4; nt++) {
                float e;
                e = c[mt][nt][0] + bv0; s0 += (e >= 0.f) ? e : 0.2f * e;
                e = c[mt][nt][1] + bv0; s0 += (e >= 0.f) ? e : 0.2f * e;
                e = c[mt][nt][2] + bv1; s1 += (e >= 0.f) ? e : 0.2f * e;
                e = c[mt][nt][3] + bv1; s1 += (e >= 0.f) ? e : 0.2f * e;
            }
            s0 += __shfl_xor_sync(0xffffffffu, s0, 1);
            s0 += __shfl_xor_sync(0xffffffffu, s0, 2);
            s1 += __shfl_xor_sync(0xffffffffu, s1, 1);
            s1 += __shfl_xor_sync(0xffffffffu, s1, 2);
            if (tig == 0) {
                atomicAdd(&g_M[bt * DD + jr], s0);
                atomicAdd(&g_M[bt * DD + jr + 8], s1);
            }
        }
    }

    // ======================= Phase 4: last-CTA final GEMV ====================
    __threadfence();           // publish our g_M contributions
    __syncthreads();
    if (tid == 0) s_last = atomicAdd(&g_cnt[bt], 1u);
    __syncthreads();
    if (s_last == 3u) {        // all 4 CTAs of this batch contributed
        __threadfence();       // acquire: make their g_M writes visible
        if (tid < 128) sm_m[tid] = g_M[bt * DD + tid] * (1.f / (float)TT);
        __syncthreads();
        if (tid < 128) {
            float s = b2[tid];
            const float* wr = w2 + tid * DD;
#pragma unroll 16
            for (int j = 0; j < DD; j++) s = fmaf(sm_m[j], wr[j], s);
            out[bt * DD + tid] = s;
        }
    }
}

// ----------------------------------------------------------------------------
extern "C" void kernel_launch(void* const* d_in, const int* in_sizes, int n_in,
                              void* d_out, int out_size)
{
    const float* x      = (const float*)d_in[0];
    const float* fc1_w  = (const float*)d_in[1];
    const float* fc1_b  = (const float*)d_in[2];
    const float* wih_f  = (const float*)d_in[3];
    const float* whh_f  = (const float*)d_in[4];
    const float* bih_f  = (const float*)d_in[5];
    const float* bhh_f  = (const float*)d_in[6];
    const float* wih_b  = (const float*)d_in[7];
    const float* whh_b  = (const float*)d_in[8];
    const float* bih_b  = (const float*)d_in[9];
    const float* bhh_b  = (const float*)d_in[10];
    const float* lout_w = (const float*)d_in[11];
    const float* lout_b = (const float*)d_in[12];
    const float* emb_w1 = (const float*)d_in[13];
    const float* emb_b1 = (const float*)d_in[14];
    const float* emb_w2 = (const float*)d_in[15];
    const float* emb_b2 = (const float*)d_in[16];
    float* out = (float*)d_out;

    cudaFuncSetAttribute(mega_kernel,
                         cudaFuncAttributeMaxDynamicSharedMemorySize, MEGA_B);

    prep_kernel<<<64, 256>>>(fc1_w, emb_w1);
    mega_kernel<<<dim3(TT / 128, BB), 256, MEGA_B>>>(
        x, fc1_b,
        wih_f, whh_f, bih_f, bhh_f,
        wih_b, whh_b, bih_b, bhh_b,
        lout_w, lout_b, emb_b1,
        emb_w2, emb_b2, out);
}

// round 17
// speedup vs baseline: 1.0821x; 1.0821x over previous
#include <cuda_runtime.h>
#include <cstdint>

// Problem constants
#define BB   64
#define TT   512
#define NTOT 32768      // BB*TT
#define FF   1024
#define DD   128

// Scratch (device globals; no allocation allowed)
__device__ float g_M[BB * DD];          // sum over t of lrelu(e1)
__device__ unsigned g_wb[DD * (FF/2)];  // fc1_w bf16x2, layout [m][k2]
__device__ unsigned g_w1hi[DD * 64];    // emb_w1 hi bf16x2, layout [j][k2]
__device__ unsigned g_w1lo[DD * 64];    // emb_w1 lo residual bf16x2

// ---------------------------------------------------------------- helpers
__device__ __forceinline__ float mtanh(float x) {
    float y;
    asm("tanh.approx.f32 %0, %1;" : "=f"(y) : "f"(x));
    return y;
}
__device__ __forceinline__ unsigned sptr(const void* p) {
    return (unsigned)__cvta_generic_to_shared(p);
}
__device__ __forceinline__ void cp16(unsigned dst, const void* src) {
    asm volatile("cp.async.cg.shared.global [%0], [%1], 16;" :: "r"(dst), "l"(src));
}
#define CP_COMMIT() asm volatile("cp.async.commit_group;")
#define CP_WAIT0()  asm volatile("cp.async.wait_group 0;")

__device__ __forceinline__ unsigned pack_bf2(float kodd, float keven) {
    unsigned d;
    asm("cvt.rn.bf16x2.f32 %0, %1, %2;" : "=r"(d) : "f"(kodd), "f"(keven));
    return d;
}
__device__ __forceinline__ float bf_lo_val(unsigned p) { return __uint_as_float(p << 16); }
__device__ __forceinline__ float bf_hi_val(unsigned p) { return __uint_as_float(p & 0xffff0000u); }
__device__ __forceinline__ unsigned hadd2(unsigned a, unsigned b) {
    unsigned d;
    asm("add.rn.bf16x2 %0, %1, %2;" : "=r"(d) : "r"(a), "r"(b));
    return d;
}
__device__ __forceinline__ void ldsm_x4(unsigned r[4], unsigned addr) {
    asm volatile("ldmatrix.sync.aligned.m8n8.x4.shared.b16 {%0,%1,%2,%3}, [%4];"
                 : "=r"(r[0]), "=r"(r[1]), "=r"(r[2]), "=r"(r[3]) : "r"(addr));
}
__device__ __forceinline__ void mma_bf16(float c[4], const unsigned a[4], const unsigned b[2]) {
    asm volatile(
        "mma.sync.aligned.m16n8k16.row.col.f32.bf16.bf16.f32 "
        "{%0,%1,%2,%3}, {%4,%5,%6,%7}, {%8,%9}, {%0,%1,%2,%3};"
        : "+f"(c[0]), "+f"(c[1]), "+f"(c[2]), "+f"(c[3])
        : "r"(a[0]), "r"(a[1]), "r"(a[2]), "r"(a[3]), "r"(b[0]), "r"(b[1]));
}

// ============================================================================
// Kernel 0: prep — fc1_w -> g_wb [m][k2] via float4 (8 k-values / thread);
// emb_w1 -> hi/lo split; zero g_M.
// ============================================================================
__global__ __launch_bounds__(256) void prep_kernel(const float* __restrict__ w,
                                                   const float* __restrict__ w1)
{
    const int t = blockIdx.x * 256 + threadIdx.x;   // 0..16383
    {
        const float4 a = *reinterpret_cast<const float4*>(w + (size_t)t * 8);
        const float4 b = *reinterpret_cast<const float4*>(w + (size_t)t * 8 + 4);
        const int m  = t >> 7;              // 0..127
        const int k2 = (t & 127) * 4;       // 0..508
        unsigned* dst = g_wb + m * 512 + k2;
        dst[0] = pack_bf2(a.y, a.x);
        dst[1] = pack_bf2(a.w, a.z);
        dst[2] = pack_bf2(b.y, b.x);
        dst[3] = pack_bf2(b.w, b.z);
    }
    if (t < DD * 64) {
        const int j  = t >> 6;
        const int k2 = t & 63;
        const float a0 = w1[j * DD + 2 * k2];
        const float a1 = w1[j * DD + 2 * k2 + 1];
        const unsigned hi = pack_bf2(a1, a0);
        const float l0 = a0 - bf_lo_val(hi);
        const float l1 = a1 - bf_hi_val(hi);
        g_w1hi[t] = hi;
        g_w1lo[t] = pack_bf2(l1, l0);
    }
    if (t < BB * DD) g_M[t] = 0.f;
}

// ============================================================================
// MEGAKERNEL: fc1 (bf16 HMMA) -> bi-LSTM -> emb1 (bf16 split HMMA), fused.
// (R15 body, proven at 78.3us total.)
// ============================================================================
#define P1A_U 2560                 // 128 rows x 20 (phase-1 A stage)
#define P1B_U 2176                 // 16 rows x 136 (phase-1 B stage)
#define RING_U (2*P1A_U + 2*P1B_U) // 9472 uints
#define SG_ST 65                   // G smem row stride (u32 pairs, padded)
#define P3A_U 1536                 // 128 rows x 12 (phase-3 A stage; reuses G region)
#define SY_ST 136
#define SY_U  (64 * SY_ST)         // 8704 uints per Y buffer
#define MEGA_U (RING_U + 2 * SY_U) // 26880 uints
#define MEGA_B (MEGA_U * 4)        // 107520 bytes

__global__ __launch_bounds__(256, 2) void mega_kernel(
    const float* __restrict__ x,    const float* __restrict__ fc1_b,
    const float* __restrict__ wih_f, const float* __restrict__ whh_f,
    const float* __restrict__ bih_f, const float* __restrict__ bhh_f,
    const float* __restrict__ wih_b, const float* __restrict__ whh_b,
    const float* __restrict__ bih_b, const float* __restrict__ bhh_b,
    const float* __restrict__ lout_w, const float* __restrict__ lout_b,
    const float* __restrict__ b1v)
{
    extern __shared__ __align__(16) unsigned smu[];
    unsigned* A_[2]; unsigned* B_[2];
    A_[0] = smu;             A_[1] = smu + P1A_U;
    B_[0] = smu + 2 * P1A_U; B_[1] = smu + 2 * P1A_U + P1B_U;
    unsigned* sG  = smu;                 // phase-1 epilogue .. phase-2 (8320 u)
    unsigned* sYf = smu + RING_U;
    unsigned* sYb = smu + RING_U + SY_U;

    const int tid  = threadIdx.x;
    const int lane = tid & 31;
    const int wid  = tid >> 5;
    const int g    = lane >> 2;
    const int tig  = lane & 3;
    const int wm   = (wid & 1) * 64;
    const int wn   = (wid >> 1) * 32;

    const int bt = blockIdx.y;
    const int t0 = blockIdx.x * 128;
    const float* xb = x + (size_t)bt * FF * TT;

    const int rowA  = tid >> 1;
    const int halfA = (tid & 1) * 8;
    const int kr = tid >> 4;
    const int q8 = (tid & 15) * 8;

    const unsigned lrow = wm + (lane & 7) + ((lane >> 3) & 1) * 8;
    const unsigned lak  = ((lane >> 4) & 1) * 4;

    float c[4][4][4];
#pragma unroll
    for (int i = 0; i < 4; i++)
#pragma unroll
        for (int j = 0; j < 4; j++)
#pragma unroll
            for (int k = 0; k < 4; k++) c[i][j][k] = 0.f;

    // ======================= Phase 1: fc1 GEMM =======================
    {
        const int NS = FF / 32;   // 32 stages

        // prologue: A(0)
        {
            const unsigned* srcA = g_wb + rowA * 512 + halfA;
            unsigned dst = sptr(A_[0] + rowA * 20 + halfA);
            cp16(dst, srcA); cp16(dst + 16, srcA + 4);
            CP_COMMIT();
        }
        float4 u0, u1, v0, v1;
        {
            const float* xp = xb + (size_t)(2 * kr) * TT + t0 + q8;
            u0 = *reinterpret_cast<const float4*>(xp);
            u1 = *reinterpret_cast<const float4*>(xp + 4);
            v0 = *reinterpret_cast<const float4*>(xp + TT);
            v1 = *reinterpret_cast<const float4*>(xp + TT + 4);
        }

        for (int s = 0; s < NS; s++) {
            // pack + store B(s)
            {
                unsigned* bp = B_[s & 1] + kr * 136 + q8;
                const float ue[8] = {u0.x, u0.y, u0.z, u0.w, u1.x, u1.y, u1.z, u1.w};
                const float vo[8] = {v0.x, v0.y, v0.z, v0.w, v1.x, v1.y, v1.z, v1.w};
                unsigned h[8];
#pragma unroll
                for (int i = 0; i < 8; i++) h[i] = pack_bf2(vo[i], ue[i]);
                *reinterpret_cast<uint4*>(bp)     = make_uint4(h[0], h[1], h[2], h[3]);
                *reinterpret_cast<uint4*>(bp + 4) = make_uint4(h[4], h[5], h[6], h[7]);
            }
            CP_WAIT0();          // A(s) landed
            __syncthreads();     // B(s) visible; buffer (s+1)&1 free

            if (s + 1 < NS) {
                const unsigned* srcA = g_wb + rowA * 512 + (s + 1) * 16 + halfA;
                unsigned dst = sptr(A_[(s + 1) & 1] + rowA * 20 + halfA);
                cp16(dst, srcA); cp16(dst + 16, srcA + 4);
            }
            CP_COMMIT();

            // prefetch B(s+1)
            {
                const int sn = (s + 1 < NS) ? s + 1 : s;
                const float* xp = xb + (size_t)(sn * 32 + 2 * kr) * TT + t0 + q8;
                u0 = *reinterpret_cast<const float4*>(xp);
                u1 = *reinterpret_cast<const float4*>(xp + 4);
                v0 = *reinterpret_cast<const float4*>(xp + TT);
                v1 = *reinterpret_cast<const float4*>(xp + TT + 4);
            }

            const unsigned Abase = sptr(A_[s & 1]);
            const unsigned* B = B_[s & 1];
#pragma unroll
            for (int g16 = 0; g16 < 2; g16++) {
                unsigned a[4][4], b[4][2];
#pragma unroll
                for (int mt = 0; mt < 4; mt++) {
                    const unsigned ad = Abase + ((lrow + mt * 16) * 20 + g16 * 8 + lak) * 4;
                    ldsm_x4(a[mt], ad);
                }
#pragma unroll
                for (int nt = 0; nt < 4; nt++) {
                    const int n = wn + nt * 8 + g;
                    b[nt][0] = B[(g16 * 8 + tig) * 136 + n];
                    b[nt][1] = B[(g16 * 8 + tig + 4) * 136 + n];
                }
#pragma unroll
                for (int mt = 0; mt < 4; mt++)
#pragma unroll
                    for (int nt = 0; nt < 4; nt++)
                        mma_bf16(c[mt][nt], a[mt], b[nt]);
            }
        }

        CP_WAIT0();
        __syncthreads();   // all MMAs done: ring region reusable as sG

        // epilogue: bias + pack to bf16 n-pairs in smem sG[d][n2]
#pragma unroll
        for (int mt = 0; mt < 4; mt++) {
            const int dr = wm + mt * 16 + g;
            const float bv0 = fc1_b[dr];
            const float bv1 = fc1_b[dr + 8];
#pragma unroll
            for (int nt = 0; nt < 4; nt++) {
                const int n2 = (wn + nt * 8) / 2 + tig;   // n-pair column
                sG[dr * SG_ST + n2] =
                    pack_bf2(c[mt][nt][1] + bv0, c[mt][nt][0] + bv0);
                sG[(dr + 8) * SG_ST + n2] =
                    pack_bf2(c[mt][nt][3] + bv1, c[mt][nt][2] + bv1);
            }
        }
    }
    __syncthreads();   // sG complete

    // ======================= Phase 2: bi-LSTM (smem-resident) ================
    {
        const int dir = tid >> 7;          // 0 fwd, 1 bwd
        const int nl  = tid & 127;

        const float* wih = dir ? wih_b : wih_f;
        const float* whh = dir ? whh_b : whh_f;
        const float* bih = dir ? bih_b : bih_f;
        const float* bhh = dir ? bhh_b : bhh_f;

        const float wi0 = 0.5f * wih[0], wh0 = 0.5f * whh[0], b0 = 0.5f * (bih[0] + bhh[0]);
        const float wi1 = 0.5f * wih[1], wh1 = 0.5f * whh[1], b1 = 0.5f * (bih[1] + bhh[1]);
        const float wi2 =        wih[2], wh2 =        whh[2], b2 =        (bih[2] + bhh[2]);
        const float wi3 = 0.5f * wih[3], wh3 = 0.5f * whh[3], b3 = 0.5f * (bih[3] + bhh[3]);

        const float lw = dir ? lout_w[1] : lout_w[0];
        const float lb = dir ? 0.f : lout_b[0];

        const int gst = dir ? -SG_ST : SG_ST;
        const unsigned* gp = sG + (dir ? 127 * SG_ST : 0) + (nl >> 1);
        const bool hi_half = (nl & 1);

        unsigned* yw = (dir ? (sYb + 63 * SY_ST) : sYf) + nl;
        const int yst = dir ? -SY_ST : SY_ST;

        float h = 0.f, cc = 0.f, yprev = 0.f;

#pragma unroll 8
        for (int it = 0; it < DD; it++) {
            const unsigned gw = *gp;
            gp += gst;
            const float xv = hi_half ? bf_hi_val(gw) : bf_lo_val(gw);

            const float ai = fmaf(wi0, xv, fmaf(wh0, h, b0));
            const float af = fmaf(wi1, xv, fmaf(wh1, h, b1));
            const float ag = fmaf(wi2, xv, fmaf(wh2, h, b2));
            const float ao = fmaf(wi3, xv, fmaf(wh3, h, b3));

            const float si = fmaf(0.5f, mtanh(ai), 0.5f);
            const float sf = fmaf(0.5f, mtanh(af), 0.5f);
            const float tg = mtanh(ag);
            const float so = fmaf(0.5f, mtanh(ao), 0.5f);

            cc = fmaf(sf, cc, si * tg);
            h = so * mtanh(cc);

            const float y = fmaf(lw, h, lb);
            if (it & 1) {
                *yw = dir ? pack_bf2(yprev, y) : pack_bf2(y, yprev);
                yw += yst;
            } else {
                yprev = y;
            }
        }
    }
    __syncthreads();   // sYf / sYb ready; sG dead

    // ======================= Phase 3: emb1 =======================
    {
        unsigned* AH_[2]; unsigned* AL_[2];
        AH_[0] = smu;             AH_[1] = smu + P3A_U;
        AL_[0] = smu + 2 * P3A_U; AL_[1] = smu + 3 * P3A_U;

        const int rowW  = tid >> 1;
        const int halfW = (tid & 1) * 4;

#pragma unroll
        for (int i = 0; i < 4; i++)
#pragma unroll
            for (int j = 0; j < 4; j++)
#pragma unroll
                for (int k = 0; k < 4; k++) c[i][j][k] = 0.f;

        // prologue: stage 0
        cp16(sptr(AH_[0] + rowW * 12 + halfW), g_w1hi + rowW * 64 + halfW);
        cp16(sptr(AL_[0] + rowW * 12 + halfW), g_w1lo + rowW * 64 + halfW);
        CP_COMMIT();

        for (int s = 0; s < 8; s++) {        // 8 stages of 8 k2-rows (k16 each)
            CP_WAIT0();          // A(s) landed
            __syncthreads();     // all warps past MMA(s-1): buffer (s+1)&1 free

            if (s + 1 < 8) {
                cp16(sptr(AH_[(s + 1) & 1] + rowW * 12 + halfW),
                     g_w1hi + rowW * 64 + (s + 1) * 8 + halfW);
                cp16(sptr(AL_[(s + 1) & 1] + rowW * 12 + halfW),
                     g_w1lo + rowW * 64 + (s + 1) * 8 + halfW);
            }
            CP_COMMIT();

            const unsigned AHb = sptr(AH_[s & 1]);
            const unsigned ALb = sptr(AL_[s & 1]);

            unsigned ah[4][4], al[4][4], b[4][2];
#pragma unroll
            for (int mt = 0; mt < 4; mt++) {
                const unsigned off = ((lrow + mt * 16) * 12 + lak) * 4;
                ldsm_x4(ah[mt], AHb + off);
                ldsm_x4(al[mt], ALb + off);
            }
#pragma unroll
            for (int nt = 0; nt < 4; nt++) {
                const int n = wn + nt * 8 + g;
                b[nt][0] = hadd2(sYf[(s * 8 + tig) * SY_ST + n],
                                 sYb[(s * 8 + tig) * SY_ST + n]);
                b[nt][1] = hadd2(sYf[(s * 8 + tig + 4) * SY_ST + n],
                                 sYb[(s * 8 + tig + 4) * SY_ST + n]);
            }
#pragma unroll
            for (int mt = 0; mt < 4; mt++)
#pragma unroll
                for (int nt = 0; nt < 4; nt++) {
                    mma_bf16(c[mt][nt], ah[mt], b[nt]);
                    mma_bf16(c[mt][nt], al[mt], b[nt]);
                }
        }

        // epilogue: bias + leaky-relu + sum over n, quad-reduce, atomicAdd
#pragma unroll
        for (int mt = 0; mt < 4; mt++) {
            const int jr = wm + mt * 16 + g;
            const float bv0 = b1v[jr];
            const float bv1 = b1v[jr + 8];
            float s0 = 0.f, s1 = 0.f;
#pragma unroll
            for (int nt = 0; nt < 4; nt++) {
                float e;
                e = c[mt][nt][0] + bv0; s0 += (e >= 0.f) ? e : 0.2f * e;
                e = c[mt][nt][1] + bv0; s0 += (e >= 0.f) ? e : 0.2f * e;
                e = c[mt][nt][2] + bv1; s1 += (e >= 0.f) ? e : 0.2f * e;
                e = c[mt][nt][3] + bv1; s1 += (e >= 0.f) ? e : 0.2f * e;
            }
            s0 += __shfl_xor_sync(0xffffffffu, s0, 1);
            s0 += __shfl_xor_sync(0xffffffffu, s0, 2);
            s1 += __shfl_xor_sync(0xffffffffu, s1, 1);
            s1 += __shfl_xor_sync(0xffffffffu, s1, 2);
            if (tig == 0) {
                atomicAdd(&g_M[bt * DD + jr], s0);
                atomicAdd(&g_M[bt * DD + jr + 8], s1);
            }
        }
    }
}

// ============================================================================
// Kernel 4: out[b][i] = (1/T) * sum_j g_M[b][j] * emb_w2[i][j] + emb_b2[i]
// ============================================================================
__global__ __launch_bounds__(128) void out_kernel(const float* __restrict__ w2,
                                                  const float* __restrict__ b2,
                                                  float* __restrict__ out)
{
    __shared__ float m[128];
    const int b = blockIdx.x;
    const int i = threadIdx.x;
    m[i] = g_M[b * DD + i] * (1.f / (float)TT);
    __syncthreads();
    float s = b2[i];
    const float* wr = w2 + i * DD;
#pragma unroll 16
    for (int j = 0; j < DD; j++) s = fmaf(m[j], wr[j], s);
    out[b * DD + i] = s;
}

// ----------------------------------------------------------------------------
extern "C" void kernel_launch(void* const* d_in, const int* in_sizes, int n_in,
                              void* d_out, int out_size)
{
    const float* x      = (const float*)d_in[0];
    const float* fc1_w  = (const float*)d_in[1];
    const float* fc1_b  = (const float*)d_in[2];
    const float* wih_f  = (const float*)d_in[3];
    const float* whh_f  = (const float*)d_in[4];
    const float* bih_f  = (const float*)d_in[5];
    const float* bhh_f  = (const float*)d_in[6];
    const float* wih_b  = (const float*)d_in[7];
    const float* whh_b  = (const float*)d_in[8];
    const float* bih_b  = (const float*)d_in[9];
    const float* bhh_b  = (const float*)d_in[10];
    const float* lout_w = (const float*)d_in[11];
    const float* lout_b = (const float*)d_in[12];
    const float* emb_w1 = (const float*)d_in[13];
    const float* emb_b1 = (const float*)d_in[14];
    const float* emb_w2 = (const float*)d_in[15];
    const float* emb_b2 = (const float*)d_in[16];
    float* out = (float*)d_out;

    cudaFuncSetAttribute(mega_kernel,
                         cudaFuncAttributeMaxDynamicSharedMemorySize, MEGA_B);

    prep_kernel<<<64, 256>>>(fc1_w, emb_w1);
    mega_kernel<<<dim3(TT / 128, BB), 256, MEGA_B>>>(
        x, fc1_b,
        wih_f, whh_f, bih_f, bhh_f,
        wih_b, whh_b, bih_b, bhh_b,
        lout_w, lout_b, emb_b1);
    out_kernel<<<BB, 128>>>(emb_w2, emb_b2, out);
}